// round 17
// baseline (speedup 1.0000x reference)
#include <cuda_runtime.h>
#include <cuda_fp16.h>
#include <cstdint>

#define DIM      64
#define KC       512
#define NBLK     152
#define THREADS  512
#define TILE     64
#define SSTR     516

// ---- SMEM layout (bytes); tile bases 1024-aligned for SW128 ----
#define SM_CTR   0
#define SM_SEMAX 8
#define SM_SE    64
#define SM_A     3072                      // 64 x 128B fp16 z-tile
#define SM_B     11264                     // 512 x 128B fp16 codebook
#define SM_SCR   76800                     // 64 x 516 fp32 screen (132096B)
#define SM_RED   (SM_SCR + 132096)         // 16 fp32 loss partials
#define SMEM_TOTAL 208960

__device__ double   g_loss_sum;
__device__ unsigned g_work_ctr;
__device__ unsigned g_cta_done;
__device__ float    g_bi_scratch[1 << 17];

__device__ __forceinline__ uint32_t smem_u32(const void* p) {
    uint32_t a;
    asm("{ .reg .u64 t; cvta.to.shared.u64 t, %1; cvt.u32.u64 %0, t; }" : "=r"(a) : "l"(p));
    return a;
}
#define SW128(o) ((o) ^ (((o) >> 3) & 0x70))

__device__ __forceinline__ void ldmatrix_x4(uint32_t& a0, uint32_t& a1,
                                            uint32_t& a2, uint32_t& a3, uint32_t addr) {
    asm volatile("ldmatrix.sync.aligned.m8n8.x4.shared.b16 {%0,%1,%2,%3}, [%4];"
                 : "=r"(a0), "=r"(a1), "=r"(a2), "=r"(a3) : "r"(addr));
}
__device__ __forceinline__ void mma_f16(float* c, const uint32_t* a,
                                        uint32_t b0, uint32_t b1) {
    asm volatile("mma.sync.aligned.m16n8k16.row.col.f32.f16.f16.f32 "
                 "{%0,%1,%2,%3},{%4,%5,%6,%7},{%8,%9},{%0,%1,%2,%3};"
                 : "+f"(c[0]), "+f"(c[1]), "+f"(c[2]), "+f"(c[3])
                 : "r"(a[0]), "r"(a[1]), "r"(a[2]), "r"(a[3]), "r"(b0), "r"(b1));
}

// BITWISE-CRITICAL exact distance: sequential rn chain ascending d,
// dist = fl(fl(sz + se_k) - 2*dot). Identical rounding to validated R3 chain.
__device__ __forceinline__ float exact_dist(const float* __restrict__ zrow, float sz,
                                            const float* __restrict__ emb,
                                            const float* se, int k) {
    const float4* e = (const float4*)(emb + k * DIM);
    const float4* zp = (const float4*)zrow;
    float a = 0.0f;
    #pragma unroll
    for (int i = 0; i < 16; i++) {
        float4 ev = e[i];
        float4 zv = zp[i];
        a = __fmaf_rn(zv.x, ev.x, a);
        a = __fmaf_rn(zv.y, ev.y, a);
        a = __fmaf_rn(zv.z, ev.z, a);
        a = __fmaf_rn(zv.w, ev.w, a);
    }
    return __fsub_rn(__fadd_rn(sz, se[k]), 2.0f * a);
}

__global__ __launch_bounds__(THREADS, 1)
void vq_main_kernel(const float* __restrict__ z,
                    const float* __restrict__ emb,
                    float* __restrict__ out,
                    int M, long long zn,
                    long long q_off, long long i_off,
                    int has_q, int has_idx, int has_loss)
{
    extern __shared__ char smc[];
    const uint32_t sb = smem_u32(smc);
    const int tid = threadIdx.x, wid = tid >> 5, lane = tid & 31;
    float* se   = (float*)(smc + SM_SE);
    float* scr  = (float*)(smc + SM_SCR);
    float* lred = (float*)(smc + SM_RED);

    // One-time: fp16 codebook (SW128) + ||e||^2 sequential rn.
    for (int i = tid; i < KC * 32; i += THREADS) {
        int k = i >> 5, d2 = i & 31;
        float2 v = ((const float2*)emb)[k * 32 + d2];
        uint32_t off = SW128((uint32_t)(k * 128 + d2 * 4));
        *(__half2*)(smc + SM_B + off) = __float22half2_rn(v);
    }
    for (int k = tid; k < KC; k += THREADS) {
        const float* e = emb + k * DIM;
        float s = 0.0f;
        #pragma unroll
        for (int d = 0; d < DIM; d++) s = __fadd_rn(s, __fmul_rn(e[d], e[d]));
        se[k] = s;
    }
    __syncthreads();
    if (tid == 0) {
        float mx = 0.0f;
        for (int k = 0; k < KC; k++) mx = fmaxf(mx, se[k]);
        *(float*)(smc + SM_SEMAX) = sqrtf(mx);
    }
    __syncthreads();
    const float semax_s = *(float*)(smc + SM_SEMAX);

    const int a_m  = (lane & 7) + ((lane & 8) ? 8 : 0);
    const int a_kb = (lane & 16) ? 16 : 0;
    const int b_n  = (lane & 7) + ((lane & 16) ? 8 : 0);
    const int b_kb = (lane & 8) ? 16 : 0;

    float* idx_dst = has_idx ? (out + i_off) : g_bi_scratch;
    const int ntiles = (M + TILE - 1) / TILE;
    float loss_acc = 0.0f;      // per-thread across tiles

    for (;;) {
        if (tid == 0)
            *(volatile unsigned*)(smc + SM_CTR) = atomicAdd(&g_work_ctr, 1u);
        __syncthreads();
        unsigned tile = *(volatile unsigned*)(smc + SM_CTR);
        if (tile >= (unsigned)ntiles) break;
        const int row0 = (int)tile * TILE;

        // A tile: 64 z-rows -> fp16 SW128.
        for (int i = tid; i < TILE * 32; i += THREADS) {
            int r = i >> 5, d2 = i & 31;
            int gr = row0 + r;
            float2 v = (gr < M) ? ((const float2*)z)[(size_t)gr * 32 + d2]
                                : make_float2(0.f, 0.f);
            uint32_t off = SW128((uint32_t)(r * 128 + d2 * 4));
            *(__half2*)(smc + SM_A + off) = __float22half2_rn(v);
        }
        __syncthreads();

        // Screen: warp w -> m-tile (w&3)*16, n-quarter (w>>2)*128.
        {
            const int m0 = (wid & 3) * 16;
            const int nb = (wid >> 2) * 128;
            uint32_t a[16];
            #pragma unroll
            for (int ks = 0; ks < 4; ks++) {
                uint32_t o = SW128((uint32_t)((m0 + a_m) * 128 + ks * 32 + a_kb));
                ldmatrix_x4(a[4*ks], a[4*ks+1], a[4*ks+2], a[4*ks+3], sb + SM_A + o);
            }
            const int g  = lane >> 2;
            const int cp = (lane & 3) * 2;
            #pragma unroll
            for (int nt = 0; nt < 8; nt++) {
                const int n0 = nb + nt * 16;
                float c0[4] = {0.f,0.f,0.f,0.f}, c1[4] = {0.f,0.f,0.f,0.f};
                #pragma unroll
                for (int ks = 0; ks < 4; ks++) {
                    uint32_t o = SW128((uint32_t)((n0 + b_n) * 128 + ks * 32 + b_kb));
                    uint32_t h0,h1,h2,h3;
                    ldmatrix_x4(h0,h1,h2,h3, sb + SM_B + o);
                    mma_f16(c0, a + 4*ks, h0, h1);
                    mma_f16(c1, a + 4*ks, h2, h3);
                }
                int colA = n0 + cp, colB = n0 + 8 + cp;
                *(float2*)(scr + (m0+g)  *SSTR + colA) =
                    make_float2(fmaf(-2.f, c0[0], se[colA]), fmaf(-2.f, c0[1], se[colA+1]));
                *(float2*)(scr + (m0+g+8)*SSTR + colA) =
                    make_float2(fmaf(-2.f, c0[2], se[colA]), fmaf(-2.f, c0[3], se[colA+1]));
                *(float2*)(scr + (m0+g)  *SSTR + colB) =
                    make_float2(fmaf(-2.f, c1[0], se[colB]), fmaf(-2.f, c1[1], se[colB+1]));
                *(float2*)(scr + (m0+g+8)*SSTR + colB) =
                    make_float2(fmaf(-2.f, c1[2], se[colB]), fmaf(-2.f, c1[3], se[colB+1]));
            }
        }
        __syncthreads();

        // Owner phase (+ fused quantize/loss): 8 threads/row.
        {
            const int row = tid >> 3, stripe = tid & 7;
            const int gr = row0 + row;
            if (gr < M) {
                const float* zrow = z + (size_t)gr * DIM;
                float sz = 0.0f;
                if (stripe == 0) {
                    const float4* zp = (const float4*)zrow;
                    #pragma unroll
                    for (int i = 0; i < 16; i++) {
                        float4 v = zp[i];
                        sz = __fadd_rn(sz, __fmul_rn(v.x, v.x));
                        sz = __fadd_rn(sz, __fmul_rn(v.y, v.y));
                        sz = __fadd_rn(sz, __fmul_rn(v.z, v.z));
                        sz = __fadd_rn(sz, __fmul_rn(v.w, v.w));
                    }
                }
                sz = __shfl_sync(0xffffffffu, sz, (lane & 24));

                const float4* srow = (const float4*)(scr + row * SSTR + stripe * 64);
                // Rotated scan: jr = (j + 2*stripe) & 15 de-conflicts stripe banks.
                float lmin = 3.402823466e38f;
                #pragma unroll
                for (int j = 0; j < 16; j++) {
                    float4 s = srow[(j + 2 * stripe) & 15];
                    lmin = fminf(lmin, fminf(fminf(s.x, s.y), fminf(s.z, s.w)));
                }
                #pragma unroll
                for (int o = 1; o < 8; o <<= 1)
                    lmin = fminf(lmin, __shfl_xor_sync(0xffffffffu, lmin, o));
                const float thr = lmin + 0.00390625f * sqrtf(sz) * semax_s + 5e-5f;

                float best = 3.402823466e38f; int bik = 0x7fffffff;
                int cand[4]; int nc = 0; bool ovf = false;
                const int cb = stripe * 64;
                #pragma unroll
                for (int j = 0; j < 16; j++) {
                    int jr = (j + 2 * stripe) & 15;
                    float4 s = srow[jr];
                    if (s.x < thr) { if (nc < 4) cand[nc++] = cb + 4*jr;   else ovf = true; }
                    if (s.y < thr) { if (nc < 4) cand[nc++] = cb + 4*jr+1; else ovf = true; }
                    if (s.z < thr) { if (nc < 4) cand[nc++] = cb + 4*jr+2; else ovf = true; }
                    if (s.w < thr) { if (nc < 4) cand[nc++] = cb + 4*jr+3; else ovf = true; }
                }
                if (!ovf) {
                    for (int i = 0; i < nc; i++) {
                        int k = cand[i];
                        float dd = exact_dist(zrow, sz, emb, se, k);
                        if (dd < best || (dd == best && k < bik)) { best = dd; bik = k; }
                    }
                } else {          // rare: exact scan of this 64-code stripe
                    for (int k = cb; k < cb + 64; k++) {
                        float dd = exact_dist(zrow, sz, emb, se, k);
                        if (dd < best || (dd == best && k < bik)) { best = dd; bik = k; }
                    }
                }
                #pragma unroll
                for (int o = 1; o < 8; o <<= 1) {
                    float ob = __shfl_xor_sync(0xffffffffu, best, o);
                    int   ok = __shfl_xor_sync(0xffffffffu, bik,  o);
                    if (ob < best || (ob == best && ok < bik)) { best = ob; bik = ok; }
                }
                if (stripe == 0) idx_dst[gr] = (float)bik;

                // Fused epilogue: 8 elems/thread; z/emb rows are L1-hot.
                const float* erow = emb + bik * DIM;
                const int d0 = stripe * 8;
                float l = 0.0f;
                #pragma unroll
                for (int j = 0; j < 8; j++) {
                    float zd = zrow[d0 + j];
                    float q  = erow[d0 + j];
                    float r  = __fsub_rn(q, zd);
                    float st = __fadd_rn(zd, r);
                    if (has_q) out[q_off + (size_t)gr * DIM + d0 + j] = st;
                    float df = __fsub_rn(st, zd);
                    l = __fmaf_rn(df, df, l);
                }
                loss_acc += l;
            }
        }
        __syncthreads();
    }

    // Loss: warp -> smem -> CTA -> global; last CTA finalizes + resets scratch.
    #pragma unroll
    for (int o = 16; o; o >>= 1)
        loss_acc += __shfl_xor_sync(0xffffffffu, loss_acc, o);
    if (lane == 0) lred[wid] = loss_acc;
    __syncthreads();
    if (tid == 0) {
        double s = 0.0;
        for (int i = 0; i < 16; i++) s += (double)lred[i];
        atomicAdd(&g_loss_sum, s);
        __threadfence();
        if (atomicAdd(&g_cta_done, 1u) == gridDim.x - 1) {
            if (has_loss) out[0] = (float)(1.25 * (g_loss_sum / (double)zn));
            g_loss_sum = 0.0; g_work_ctr = 0u; g_cta_done = 0u;  // graph-replay reset
        }
    }
}

extern "C" void kernel_launch(void* const* d_in, const int* in_sizes, int n_in,
                              void* d_out, int out_size)
{
    const float* z   = (const float*)d_in[0];
    const float* emb = (const float*)d_in[1];
    long long zn = in_sizes[0];
    if (n_in >= 2 && in_sizes[0] == KC * DIM && in_sizes[1] != KC * DIM) {
        z = (const float*)d_in[1]; emb = (const float*)d_in[0]; zn = in_sizes[1];
    }
    int M = (int)(zn / DIM);
    float* out = (float*)d_out;

    long long q_off = 1, i_off = 1 + zn;
    int has_loss = 1, has_q = 1, has_idx = 1;
    long long osz = (long long)out_size;
    if (osz == 1 + zn + (long long)M)      { }
    else if (osz == zn + (long long)M)     { has_loss = 0; q_off = 0; i_off = zn; }
    else if (osz == zn)                    { has_loss = 0; has_idx = 0; q_off = 0; }
    else if (osz == 1)                     { has_q = 0; has_idx = 0; }

    cudaFuncSetAttribute(vq_main_kernel,
                         cudaFuncAttributeMaxDynamicSharedMemorySize, SMEM_TOTAL);

    // Single fused kernel: argmin + quantize + loss + scratch reset.
    vq_main_kernel<<<NBLK, THREADS, SMEM_TOTAL>>>(z, emb, out, M, zn,
                                                  q_off, i_off,
                                                  has_q, has_idx, has_loss);
}